// round 13
// baseline (speedup 1.0000x reference)
#include <cuda_runtime.h>
#include <cuda_bf16.h>
#include <cstdint>

#define BTOT 65536
#define HDIM 512
#define DDIM 64

// ---------------- static device scratch ----------------
__device__ __nv_bfloat16 g_xhi[BTOT * DDIM], g_xlo[BTOT * DDIM];
__device__ __nv_bfloat16 g_h0hi[BTOT * HDIM], g_h0lo[BTOT * HDIM];
__device__ __nv_bfloat16 g_h1hi[BTOT * HDIM], g_h1lo[BTOT * HDIM];
__device__ __nv_bfloat16 g_dAhi[BTOT * HDIM], g_dAlo[BTOT * HDIM];
__device__ __nv_bfloat16 g_dBhi[BTOT * HDIM], g_dBlo[BTOT * HDIM];

// pre-packed B fragments (uint2 = {b0,b1} regs for one n8k16 tile, per lane)
__device__ uint2 g_fW0T_hi[8192],  g_fW0T_lo[8192];    // KT=64,  NTOT=512
__device__ uint2 g_fW1T_hi[65536], g_fW1T_lo[65536];   // KT=512, NTOT=512
__device__ uint2 g_fW2T_hi[65536], g_fW2T_lo[65536];
__device__ uint2 g_fW2n_hi[65536], g_fW2n_lo[65536];
__device__ uint2 g_fW1n_hi[65536], g_fW1n_lo[65536];
__device__ uint2 g_fW0n_hi[8192],  g_fW0n_lo[8192];    // KT=512, NTOT=64

// ---------------- helpers ----------------
__device__ __forceinline__ uint32_t smem_u32(const void* p) {
    uint32_t a;
    asm("{ .reg .u64 t; cvta.to.shared.u64 t, %1; cvt.u32.u64 %0, t; }" : "=r"(a) : "l"(p));
    return a;
}
__device__ __forceinline__ uint32_t pk2(__nv_bfloat16 a, __nv_bfloat16 b) {
    return (uint32_t)__bfloat16_as_ushort(a) | ((uint32_t)__bfloat16_as_ushort(b) << 16);
}
__device__ __forceinline__ void ldsm4(uint32_t r[4], uint32_t addr) {
    asm volatile("ldmatrix.sync.aligned.m8n8.x4.shared.b16 {%0,%1,%2,%3}, [%4];"
                 : "=r"(r[0]), "=r"(r[1]), "=r"(r[2]), "=r"(r[3]) : "r"(addr));
}
__device__ __forceinline__ void mma16816(float c[4], const uint32_t a[4],
                                         uint32_t b0, uint32_t b1) {
    asm volatile(
        "mma.sync.aligned.m16n8k16.row.col.f32.bf16.bf16.f32 "
        "{%0,%1,%2,%3}, {%4,%5,%6,%7}, {%8,%9}, {%0,%1,%2,%3};"
        : "+f"(c[0]), "+f"(c[1]), "+f"(c[2]), "+f"(c[3])
        : "r"(a[0]), "r"(a[1]), "r"(a[2]), "r"(a[3]), "r"(b0), "r"(b1));
}
// split a,b (cols c, c+1) into hi u32 (returned) and lo u32 (out param)
__device__ __forceinline__ uint32_t split2(float a, float b, uint32_t& lo) {
    __nv_bfloat16 ha = __float2bfloat16(a), hb = __float2bfloat16(b);
    __nv_bfloat16 la = __float2bfloat16(a - __bfloat162float(ha));
    __nv_bfloat16 lb = __float2bfloat16(b - __bfloat162float(hb));
    lo = pk2(la, lb);
    return pk2(ha, hb);
}
__device__ __forceinline__ float bflo(uint32_t u) {
    return __bfloat162float(__ushort_as_bfloat16((unsigned short)(u & 0xFFFF)));
}
__device__ __forceinline__ float bfhi(uint32_t u) {
    return __bfloat162float(__ushort_as_bfloat16((unsigned short)(u >> 16)));
}

// ---------------- prep kernels ----------------
__global__ void split_k(const float* __restrict__ in,
                        __nv_bfloat16* __restrict__ hi, __nv_bfloat16* __restrict__ lo,
                        int n) {
    int i = blockIdx.x * blockDim.x + threadIdx.x;
    if (i < n) {
        float v = in[i];
        __nv_bfloat16 h = __float2bfloat16(v);
        hi[i] = h;
        lo[i] = __float2bfloat16(v - __bfloat162float(h));
    }
}

// Pack B[n][k] (= W[k*NTOT+n] if trans else W[n*KT+k]) into per-lane fragment order.
// uint2 index i = ((kt*nG + ng)*32 + lane)*TPW + t ;
// element n = ng*TPW*8 + t*8 + lane/4 ; k0 = kt*16 + 2*(lane&3); b0=(k0,k0+1) b1=(k0+8,k0+9)
__global__ void pack_frag(const float* __restrict__ W,
                          uint2* __restrict__ dhi, uint2* __restrict__ dlo,
                          int KT, int NTOT, int TPW, int nG, int trans) {
    int total = (KT / 16) * nG * 32 * TPW;
    for (int i = blockIdx.x * blockDim.x + threadIdx.x; i < total;
         i += gridDim.x * blockDim.x) {
        int t = i % TPW;
        int r1 = i / TPW;
        int lane = r1 & 31;
        int r2 = r1 >> 5;
        int ng = r2 % nG;
        int kt = r2 / nG;
        int n = ng * TPW * 8 + t * 8 + (lane >> 2);
        int k0 = kt * 16 + 2 * (lane & 3);
        float v[4];
#pragma unroll
        for (int j = 0; j < 4; j++) {
            int k = k0 + ((j >= 2) ? 8 : 0) + (j & 1);
            v[j] = trans ? W[(size_t)k * NTOT + n] : W[(size_t)n * KT + k];
        }
        uint32_t l0, l1;
        uint2 h, l;
        h.x = split2(v[0], v[1], l0);
        h.y = split2(v[2], v[3], l1);
        l.x = l0; l.y = l1;
        dhi[i] = h;
        dlo[i] = l;
    }
}

// ---------------- GEMM layer (mma.sync) ----------------
// D[r][n] = sum_k A[r][k]*B[n][k], 3-term bf16 split, fused epilogue.
// EPI: 0 tanh(D+bias); 1 (1-tanh^2(D+bias))*w3[n]; 2 D*(1-(Hhi+Hlo)^2); 3 symplectic fp32
template<int KT, int NTOT, int EPI>
__global__ void __launch_bounds__(512, 1)
gemm_layer(const __nv_bfloat16* __restrict__ Ahi, const __nv_bfloat16* __restrict__ Alo,
           const uint2* __restrict__ fhi, const uint2* __restrict__ flo,
           const float* __restrict__ bias, const float* __restrict__ w3,
           const __nv_bfloat16* __restrict__ Hhi, const __nv_bfloat16* __restrict__ Hlo,
           __nv_bfloat16* __restrict__ Ohi, __nv_bfloat16* __restrict__ Olo,
           float* __restrict__ Ofp) {
    constexpr int TPW = (NTOT == 512) ? 16 : 4;     // n8-tiles per warp
    constexpr int nG = NTOT / (8 * TPW);            // 4 or 2
    constexpr int NPASS = nG / 2;                   // 2 or 1
    constexpr int NKC = KT / 64;

    __shared__ __align__(16) __nv_bfloat16 sA[2][128][72];   // 72-pad: conflict-free ldmatrix

    const int tid = threadIdx.x;
    const int lane = tid & 31;
    const int w = tid >> 5;
    const int wm = w & 7;        // m16-tile: rows [16wm,16wm+16)
    const int wn = w >> 3;       // n-group half
    const long row0 = (long)blockIdx.x * 128;

    const int lrow = 16 * wm + (lane & 15);
    const int lcol8 = (lane >> 4) << 3;
    const int sr = tid >> 2;            // staging row (0..127)
    const int skq = (tid & 3) << 1;     // staging uint4 pair idx

    for (int pass = 0; pass < NPASS; pass++) {
        const int ng = pass * 2 + wn;
        float acc[TPW][4];
#pragma unroll
        for (int t = 0; t < TPW; t++)
#pragma unroll
            for (int q = 0; q < 4; q++) acc[t][q] = 0.f;

        for (int kc = 0; kc < NKC; kc++) {
            __syncthreads();
            {
                const uint4* gh = reinterpret_cast<const uint4*>(Ahi + (row0 + sr) * KT + kc * 64);
                const uint4* gl = reinterpret_cast<const uint4*>(Alo + (row0 + sr) * KT + kc * 64);
                uint4* sh = reinterpret_cast<uint4*>(&sA[0][sr][0]);
                uint4* sl = reinterpret_cast<uint4*>(&sA[1][sr][0]);
                sh[skq] = gh[skq]; sh[skq + 1] = gh[skq + 1];
                sl[skq] = gl[skq]; sl[skq + 1] = gl[skq + 1];
            }
            __syncthreads();

#pragma unroll
            for (int ks = 0; ks < 4; ks++) {
                const int ktg = kc * 4 + ks;
                uint32_t ah[4], al[4];
                ldsm4(ah, smem_u32(&sA[0][lrow][ks * 16 + lcol8]));
                ldsm4(al, smem_u32(&sA[1][lrow][ks * 16 + lcol8]));
                const size_t fb = ((size_t)(ktg * nG + ng) * 32 + lane) * TPW;
                const uint4* bh = reinterpret_cast<const uint4*>(fhi + fb);
                const uint4* bl = reinterpret_cast<const uint4*>(flo + fb);
#pragma unroll
                for (int j = 0; j < TPW / 2; j++) {
                    uint4 vh = bh[j];
                    uint4 vl = bl[j];
                    mma16816(acc[2 * j], ah, vh.x, vh.y);
                    mma16816(acc[2 * j], ah, vl.x, vl.y);
                    mma16816(acc[2 * j], al, vh.x, vh.y);
                    mma16816(acc[2 * j + 1], ah, vh.z, vh.w);
                    mma16816(acc[2 * j + 1], ah, vl.z, vl.w);
                    mma16816(acc[2 * j + 1], al, vh.z, vh.w);
                }
            }
        }

        // ---- epilogue ----
        const long rA = row0 + 16 * wm + (lane >> 2);   // rows rA, rA+8
        const int cb = ng * TPW * 8 + 2 * (lane & 3);
#pragma unroll
        for (int t = 0; t < TPW; t++) {
            const int c0 = cb + t * 8;
            float v00 = acc[t][0], v01 = acc[t][1], v10 = acc[t][2], v11 = acc[t][3];

            if (EPI == 0 || EPI == 1) {
                const float b0v = bias[c0], b1v = bias[c0 + 1];
                float t00 = tanhf(v00 + b0v), t01 = tanhf(v01 + b1v);
                float t10 = tanhf(v10 + b0v), t11 = tanhf(v11 + b1v);
                if (EPI == 1) {
                    const float w0v = w3[c0], w1v = w3[c0 + 1];
                    v00 = (1.f - t00 * t00) * w0v; v01 = (1.f - t01 * t01) * w1v;
                    v10 = (1.f - t10 * t10) * w0v; v11 = (1.f - t11 * t11) * w1v;
                } else {
                    v00 = t00; v01 = t01; v10 = t10; v11 = t11;
                }
            }
            if (EPI == 2) {
                uint32_t hh0 = *reinterpret_cast<const uint32_t*>(&Hhi[rA * NTOT + c0]);
                uint32_t hl0 = *reinterpret_cast<const uint32_t*>(&Hlo[rA * NTOT + c0]);
                uint32_t hh1 = *reinterpret_cast<const uint32_t*>(&Hhi[(rA + 8) * NTOT + c0]);
                uint32_t hl1 = *reinterpret_cast<const uint32_t*>(&Hlo[(rA + 8) * NTOT + c0]);
                float h00 = bflo(hh0) + bflo(hl0), h01 = bfhi(hh0) + bfhi(hl0);
                float h10 = bflo(hh1) + bflo(hl1), h11 = bfhi(hh1) + bfhi(hl1);
                v00 *= (1.f - h00 * h00); v01 *= (1.f - h01 * h01);
                v10 *= (1.f - h10 * h10); v11 *= (1.f - h11 * h11);
            }

            if (EPI == 3) {
                // symplectic: gradH col c -> out col (c+32)&63, negate if c<32
                const int oc = (c0 + 32) & 63;
                const float sgn = (c0 < 32) ? -1.f : 1.f;
                *reinterpret_cast<float2*>(&Ofp[rA * 64 + oc]) =
                    make_float2(sgn * v00, sgn * v01);
                *reinterpret_cast<float2*>(&Ofp[(rA + 8) * 64 + oc]) =
                    make_float2(sgn * v10, sgn * v11);
            } else {
                uint32_t lo0, lo1;
                uint32_t hi0 = split2(v00, v01, lo0);
                uint32_t hi1 = split2(v10, v11, lo1);
                *reinterpret_cast<uint32_t*>(&Ohi[rA * NTOT + c0]) = hi0;
                *reinterpret_cast<uint32_t*>(&Olo[rA * NTOT + c0]) = lo0;
                *reinterpret_cast<uint32_t*>(&Ohi[(rA + 8) * NTOT + c0]) = hi1;
                *reinterpret_cast<uint32_t*>(&Olo[(rA + 8) * NTOT + c0]) = lo1;
            }
        }
    }
}

// ---------------- launcher ----------------
extern "C" void kernel_launch(void* const* d_in, const int* in_sizes, int n_in,
                              void* d_out, int out_size) {
    // metadata order: t, x, W0, b0, W1, b1, W2, b2, W3, b3
    const float* x  = (const float*)d_in[1];
    const float* W0 = (const float*)d_in[2];
    const float* b0 = (const float*)d_in[3];
    const float* W1 = (const float*)d_in[4];
    const float* b1 = (const float*)d_in[5];
    const float* W2 = (const float*)d_in[6];
    const float* b2 = (const float*)d_in[7];
    const float* W3 = (const float*)d_in[8];
    float* out = (float*)d_out;

    __nv_bfloat16 *xhi, *xlo, *h0hi, *h0lo, *h1hi, *h1lo, *dAhi, *dAlo, *dBhi, *dBlo;
    uint2 *fW0Th, *fW0Tl, *fW1Th, *fW1Tl, *fW2Th, *fW2Tl, *fW2nh, *fW2nl, *fW1nh, *fW1nl, *fW0nh, *fW0nl;
    cudaGetSymbolAddress((void**)&xhi, g_xhi);   cudaGetSymbolAddress((void**)&xlo, g_xlo);
    cudaGetSymbolAddress((void**)&h0hi, g_h0hi); cudaGetSymbolAddress((void**)&h0lo, g_h0lo);
    cudaGetSymbolAddress((void**)&h1hi, g_h1hi); cudaGetSymbolAddress((void**)&h1lo, g_h1lo);
    cudaGetSymbolAddress((void**)&dAhi, g_dAhi); cudaGetSymbolAddress((void**)&dAlo, g_dAlo);
    cudaGetSymbolAddress((void**)&dBhi, g_dBhi); cudaGetSymbolAddress((void**)&dBlo, g_dBlo);
    cudaGetSymbolAddress((void**)&fW0Th, g_fW0T_hi); cudaGetSymbolAddress((void**)&fW0Tl, g_fW0T_lo);
    cudaGetSymbolAddress((void**)&fW1Th, g_fW1T_hi); cudaGetSymbolAddress((void**)&fW1Tl, g_fW1T_lo);
    cudaGetSymbolAddress((void**)&fW2Th, g_fW2T_hi); cudaGetSymbolAddress((void**)&fW2Tl, g_fW2T_lo);
    cudaGetSymbolAddress((void**)&fW2nh, g_fW2n_hi); cudaGetSymbolAddress((void**)&fW2nl, g_fW2n_lo);
    cudaGetSymbolAddress((void**)&fW1nh, g_fW1n_hi); cudaGetSymbolAddress((void**)&fW1nl, g_fW1n_lo);
    cudaGetSymbolAddress((void**)&fW0nh, g_fW0n_hi); cudaGetSymbolAddress((void**)&fW0nl, g_fW0n_lo);

    // prep
    split_k<<<(BTOT * DDIM + 255) / 256, 256>>>(x, xhi, xlo, BTOT * DDIM);
    // forward weights: B[n][k] = W[k][n] (trans=1); backward: B[n][k] = W[n][k] (trans=0)
    pack_frag<<<64, 256>>>(W0, fW0Th, fW0Tl, 64, 512, 16, 4, 1);
    pack_frag<<<256, 256>>>(W1, fW1Th, fW1Tl, 512, 512, 16, 4, 1);
    pack_frag<<<256, 256>>>(W2, fW2Th, fW2Tl, 512, 512, 16, 4, 1);
    pack_frag<<<256, 256>>>(W2, fW2nh, fW2nl, 512, 512, 16, 4, 0);
    pack_frag<<<256, 256>>>(W1, fW1nh, fW1nl, 512, 512, 16, 4, 0);
    pack_frag<<<64, 256>>>(W0, fW0nh, fW0nl, 512, 64, 4, 2, 0);

    const int GRID = BTOT / 128;   // 512

    // L0: h0 = tanh(x @ W0 + b0)
    gemm_layer<64, 512, 0><<<GRID, 512>>>(xhi, xlo, fW0Th, fW0Tl, b0, nullptr,
                                          nullptr, nullptr, h0hi, h0lo, nullptr);
    // L1: h1 = tanh(h0 @ W1 + b1)
    gemm_layer<512, 512, 0><<<GRID, 512>>>(h0hi, h0lo, fW1Th, fW1Tl, b1, nullptr,
                                           nullptr, nullptr, h1hi, h1lo, nullptr);
    // L2 + seed: dA = (1 - tanh^2(h1 @ W2 + b2)) * W3
    gemm_layer<512, 512, 1><<<GRID, 512>>>(h1hi, h1lo, fW2Th, fW2Tl, b2, W3,
                                           nullptr, nullptr, dAhi, dAlo, nullptr);
    // B2: dB = (dA @ W2^T) * (1 - h1^2)
    gemm_layer<512, 512, 2><<<GRID, 512>>>(dAhi, dAlo, fW2nh, fW2nl, nullptr, nullptr,
                                           h1hi, h1lo, dBhi, dBlo, nullptr);
    // B1: dA = (dB @ W1^T) * (1 - h0^2)
    gemm_layer<512, 512, 2><<<GRID, 512>>>(dBhi, dBlo, fW1nh, fW1nl, nullptr, nullptr,
                                           h0hi, h0lo, dAhi, dAlo, nullptr);
    // F: out = symplectic(dA @ W0^T)
    gemm_layer<512, 64, 3><<<GRID, 512>>>(dAhi, dAlo, fW0nh, fW0nl, nullptr, nullptr,
                                          nullptr, nullptr, nullptr, nullptr, out);
}

// round 15
// speedup vs baseline: 1.6512x; 1.6512x over previous
#include <cuda_runtime.h>
#include <cuda_bf16.h>
#include <cstdint>

#define BTOT 65536
#define HDIM 512
#define DDIM 64

// ---------------- static device scratch ----------------
__device__ __nv_bfloat16 g_xhi[BTOT * DDIM], g_xlo[BTOT * DDIM];
__device__ __nv_bfloat16 g_h0hi[BTOT * HDIM], g_h0lo[BTOT * HDIM];
__device__ __nv_bfloat16 g_h1hi[BTOT * HDIM], g_h1lo[BTOT * HDIM];
__device__ __nv_bfloat16 g_dAhi[BTOT * HDIM], g_dAlo[BTOT * HDIM];
__device__ __nv_bfloat16 g_dBhi[BTOT * HDIM], g_dBlo[BTOT * HDIM];

// pre-packed B fragments, COALESCED layout:
// uint4 index = ((ktg*nG + ng)*JT + j)*32 + lane, JT = TPW/2
// uint4 = {b0(t=2j), b1(t=2j), b0(t=2j+1), b1(t=2j+1)} for that lane
__device__ uint4 g_fW0T_hi[4096],  g_fW0T_lo[4096];    // KT=64,  NTOT=512
__device__ uint4 g_fW1T_hi[32768], g_fW1T_lo[32768];   // KT=512, NTOT=512
__device__ uint4 g_fW2T_hi[32768], g_fW2T_lo[32768];
__device__ uint4 g_fW2n_hi[32768], g_fW2n_lo[32768];
__device__ uint4 g_fW1n_hi[32768], g_fW1n_lo[32768];
__device__ uint4 g_fW0n_hi[4096],  g_fW0n_lo[4096];    // KT=512, NTOT=64

// ---------------- helpers ----------------
__device__ __forceinline__ uint32_t smem_u32(const void* p) {
    uint32_t a;
    asm("{ .reg .u64 t; cvta.to.shared.u64 t, %1; cvt.u32.u64 %0, t; }" : "=r"(a) : "l"(p));
    return a;
}
__device__ __forceinline__ uint32_t pk2(__nv_bfloat16 a, __nv_bfloat16 b) {
    return (uint32_t)__bfloat16_as_ushort(a) | ((uint32_t)__bfloat16_as_ushort(b) << 16);
}
__device__ __forceinline__ void ldsm4(uint32_t r[4], uint32_t addr) {
    asm volatile("ldmatrix.sync.aligned.m8n8.x4.shared.b16 {%0,%1,%2,%3}, [%4];"
                 : "=r"(r[0]), "=r"(r[1]), "=r"(r[2]), "=r"(r[3]) : "r"(addr));
}
__device__ __forceinline__ void mma16816(float c[4], const uint32_t a[4],
                                         uint32_t b0, uint32_t b1) {
    asm volatile(
        "mma.sync.aligned.m16n8k16.row.col.f32.bf16.bf16.f32 "
        "{%0,%1,%2,%3}, {%4,%5,%6,%7}, {%8,%9}, {%0,%1,%2,%3};"
        : "+f"(c[0]), "+f"(c[1]), "+f"(c[2]), "+f"(c[3])
        : "r"(a[0]), "r"(a[1]), "r"(a[2]), "r"(a[3]), "r"(b0), "r"(b1));
}
// split a,b (cols c, c+1) into hi u32 (returned) and lo u32 (out param)
__device__ __forceinline__ uint32_t split2(float a, float b, uint32_t& lo) {
    __nv_bfloat16 ha = __float2bfloat16(a), hb = __float2bfloat16(b);
    __nv_bfloat16 la = __float2bfloat16(a - __bfloat162float(ha));
    __nv_bfloat16 lb = __float2bfloat16(b - __bfloat162float(hb));
    lo = pk2(la, lb);
    return pk2(ha, hb);
}
__device__ __forceinline__ float bflo(uint32_t u) {
    return __bfloat162float(__ushort_as_bfloat16((unsigned short)(u & 0xFFFF)));
}
__device__ __forceinline__ float bfhi(uint32_t u) {
    return __bfloat162float(__ushort_as_bfloat16((unsigned short)(u >> 16)));
}

// ---------------- prep kernels ----------------
__global__ void split_k(const float* __restrict__ in,
                        __nv_bfloat16* __restrict__ hi, __nv_bfloat16* __restrict__ lo,
                        int n) {
    int i = blockIdx.x * blockDim.x + threadIdx.x;
    if (i < n) {
        float v = in[i];
        __nv_bfloat16 h = __float2bfloat16(v);
        hi[i] = h;
        lo[i] = __float2bfloat16(v - __bfloat162float(h));
    }
}

// Pack B[n][k] (= W[k*NTOT+n] if trans else W[n*KT+k]) into coalesced fragment order.
// uint4 i = ((kt*nG + ng)*JT + j)*32 + lane; tiles t = 2j, 2j+1;
// n = ng*TPW*8 + t*8 + lane/4; k0 = kt*16 + 2*(lane&3); pairs (k0,k0+1),(k0+8,k0+9)
__global__ void pack_frag(const float* __restrict__ W,
                          uint4* __restrict__ dhi, uint4* __restrict__ dlo,
                          int KT, int NTOT, int TPW, int nG, int trans) {
    const int JT = TPW / 2;
    const int total = (KT / 16) * nG * JT * 32;
    for (int i = blockIdx.x * blockDim.x + threadIdx.x; i < total;
         i += gridDim.x * blockDim.x) {
        int lane = i & 31;
        int r = i >> 5;
        int j = r % JT;
        int r2 = r / JT;
        int ng = r2 % nG;
        int kt = r2 / nG;
        int k0 = kt * 16 + 2 * (lane & 3);
        uint32_t h[4], l[4];
#pragma unroll
        for (int tt = 0; tt < 2; tt++) {
            int t = 2 * j + tt;
            int n = ng * TPW * 8 + t * 8 + (lane >> 2);
            float v0, v1, v2, v3;
            if (trans) {
                v0 = W[(size_t)(k0 + 0) * NTOT + n];
                v1 = W[(size_t)(k0 + 1) * NTOT + n];
                v2 = W[(size_t)(k0 + 8) * NTOT + n];
                v3 = W[(size_t)(k0 + 9) * NTOT + n];
            } else {
                v0 = W[(size_t)n * KT + k0 + 0];
                v1 = W[(size_t)n * KT + k0 + 1];
                v2 = W[(size_t)n * KT + k0 + 8];
                v3 = W[(size_t)n * KT + k0 + 9];
            }
            h[2 * tt + 0] = split2(v0, v1, l[2 * tt + 0]);
            h[2 * tt + 1] = split2(v2, v3, l[2 * tt + 1]);
        }
        dhi[i] = make_uint4(h[0], h[1], h[2], h[3]);
        dlo[i] = make_uint4(l[0], l[1], l[2], l[3]);
    }
}

// ---------------- GEMM layer (mma.sync) ----------------
// D[r][n] = sum_k A[r][k]*B[n][k], 3-term bf16 split, fused epilogue.
// EPI: 0 tanh(D+bias); 1 (1-tanh^2(D+bias))*w3[n]; 2 D*(1-(Hhi+Hlo)^2); 3 symplectic fp32
template<int KT, int NTOT, int EPI>
__global__ void __launch_bounds__(512, 1)
gemm_layer(const __nv_bfloat16* __restrict__ Ahi, const __nv_bfloat16* __restrict__ Alo,
           const uint4* __restrict__ fhi, const uint4* __restrict__ flo,
           const float* __restrict__ bias, const float* __restrict__ w3,
           const __nv_bfloat16* __restrict__ Hhi, const __nv_bfloat16* __restrict__ Hlo,
           __nv_bfloat16* __restrict__ Ohi, __nv_bfloat16* __restrict__ Olo,
           float* __restrict__ Ofp) {
    constexpr int TPW = (NTOT == 512) ? 16 : 4;     // n8-tiles per warp
    constexpr int JT = TPW / 2;
    constexpr int nG = NTOT / (8 * TPW);            // 4 or 2
    constexpr int NPASS = nG / 2;                   // 2 or 1
    constexpr int NKC = KT / 64;

    __shared__ __align__(16) __nv_bfloat16 sA[2][128][72];   // 72-pad: conflict-free ldmatrix

    const int tid = threadIdx.x;
    const int lane = tid & 31;
    const int w = tid >> 5;
    const int wm = w & 7;        // m16-tile: rows [16wm,16wm+16)
    const int wn = w >> 3;       // n-group half
    const long row0 = (long)blockIdx.x * 128;

    const int lrow = 16 * wm + (lane & 15);
    const int lcol8 = (lane >> 4) << 3;
    const int sr = tid >> 2;            // staging row (0..127)
    const int skq = (tid & 3) << 1;     // staging uint4 pair idx

    for (int pass = 0; pass < NPASS; pass++) {
        const int ng = pass * 2 + wn;
        float acc[TPW][4];
#pragma unroll
        for (int t = 0; t < TPW; t++)
#pragma unroll
            for (int q = 0; q < 4; q++) acc[t][q] = 0.f;

        for (int kc = 0; kc < NKC; kc++) {
            __syncthreads();
            {
                const uint4* gh = reinterpret_cast<const uint4*>(Ahi + (row0 + sr) * KT + kc * 64);
                const uint4* gl = reinterpret_cast<const uint4*>(Alo + (row0 + sr) * KT + kc * 64);
                uint4* sh = reinterpret_cast<uint4*>(&sA[0][sr][0]);
                uint4* sl = reinterpret_cast<uint4*>(&sA[1][sr][0]);
                sh[skq] = gh[skq]; sh[skq + 1] = gh[skq + 1];
                sl[skq] = gl[skq]; sl[skq + 1] = gl[skq + 1];
            }
            __syncthreads();

#pragma unroll
            for (int ks = 0; ks < 4; ks++) {
                const int ktg = kc * 4 + ks;
                uint32_t ah[4], al[4];
                ldsm4(ah, smem_u32(&sA[0][lrow][ks * 16 + lcol8]));
                ldsm4(al, smem_u32(&sA[1][lrow][ks * 16 + lcol8]));
                // coalesced fragment loads: 32 lanes read 32 consecutive uint4s
                const uint4* bh = fhi + (size_t)(ktg * nG + ng) * JT * 32;
                const uint4* bl = flo + (size_t)(ktg * nG + ng) * JT * 32;
#pragma unroll
                for (int j = 0; j < JT; j++) {
                    uint4 vh = bh[j * 32 + lane];
                    uint4 vl = bl[j * 32 + lane];
                    mma16816(acc[2 * j], ah, vh.x, vh.y);
                    mma16816(acc[2 * j], ah, vl.x, vl.y);
                    mma16816(acc[2 * j], al, vh.x, vh.y);
                    mma16816(acc[2 * j + 1], ah, vh.z, vh.w);
                    mma16816(acc[2 * j + 1], ah, vl.z, vl.w);
                    mma16816(acc[2 * j + 1], al, vh.z, vh.w);
                }
            }
        }

        // ---- epilogue ----
        const long rA = row0 + 16 * wm + (lane >> 2);   // rows rA, rA+8
        const int cb = ng * TPW * 8 + 2 * (lane & 3);
#pragma unroll
        for (int t = 0; t < TPW; t++) {
            const int c0 = cb + t * 8;
            float v00 = acc[t][0], v01 = acc[t][1], v10 = acc[t][2], v11 = acc[t][3];

            if (EPI == 0 || EPI == 1) {
                const float b0v = bias[c0], b1v = bias[c0 + 1];
                float t00 = tanhf(v00 + b0v), t01 = tanhf(v01 + b1v);
                float t10 = tanhf(v10 + b0v), t11 = tanhf(v11 + b1v);
                if (EPI == 1) {
                    const float w0v = w3[c0], w1v = w3[c0 + 1];
                    v00 = (1.f - t00 * t00) * w0v; v01 = (1.f - t01 * t01) * w1v;
                    v10 = (1.f - t10 * t10) * w0v; v11 = (1.f - t11 * t11) * w1v;
                } else {
                    v00 = t00; v01 = t01; v10 = t10; v11 = t11;
                }
            }
            if (EPI == 2) {
                uint32_t hh0 = *reinterpret_cast<const uint32_t*>(&Hhi[rA * NTOT + c0]);
                uint32_t hl0 = *reinterpret_cast<const uint32_t*>(&Hlo[rA * NTOT + c0]);
                uint32_t hh1 = *reinterpret_cast<const uint32_t*>(&Hhi[(rA + 8) * NTOT + c0]);
                uint32_t hl1 = *reinterpret_cast<const uint32_t*>(&Hlo[(rA + 8) * NTOT + c0]);
                float h00 = bflo(hh0) + bflo(hl0), h01 = bfhi(hh0) + bfhi(hl0);
                float h10 = bflo(hh1) + bflo(hl1), h11 = bfhi(hh1) + bfhi(hl1);
                v00 *= (1.f - h00 * h00); v01 *= (1.f - h01 * h01);
                v10 *= (1.f - h10 * h10); v11 *= (1.f - h11 * h11);
            }

            if (EPI == 3) {
                // symplectic: gradH col c -> out col (c+32)&63, negate if c<32
                const int oc = (c0 + 32) & 63;
                const float sgn = (c0 < 32) ? -1.f : 1.f;
                *reinterpret_cast<float2*>(&Ofp[rA * 64 + oc]) =
                    make_float2(sgn * v00, sgn * v01);
                *reinterpret_cast<float2*>(&Ofp[(rA + 8) * 64 + oc]) =
                    make_float2(sgn * v10, sgn * v11);
            } else {
                uint32_t lo0, lo1;
                uint32_t hi0 = split2(v00, v01, lo0);
                uint32_t hi1 = split2(v10, v11, lo1);
                *reinterpret_cast<uint32_t*>(&Ohi[rA * NTOT + c0]) = hi0;
                *reinterpret_cast<uint32_t*>(&Olo[rA * NTOT + c0]) = lo0;
                *reinterpret_cast<uint32_t*>(&Ohi[(rA + 8) * NTOT + c0]) = hi1;
                *reinterpret_cast<uint32_t*>(&Olo[(rA + 8) * NTOT + c0]) = lo1;
            }
        }
    }
}

// ---------------- launcher ----------------
extern "C" void kernel_launch(void* const* d_in, const int* in_sizes, int n_in,
                              void* d_out, int out_size) {
    // metadata order: t, x, W0, b0, W1, b1, W2, b2, W3, b3
    const float* x  = (const float*)d_in[1];
    const float* W0 = (const float*)d_in[2];
    const float* b0 = (const float*)d_in[3];
    const float* W1 = (const float*)d_in[4];
    const float* b1 = (const float*)d_in[5];
    const float* W2 = (const float*)d_in[6];
    const float* b2 = (const float*)d_in[7];
    const float* W3 = (const float*)d_in[8];
    float* out = (float*)d_out;

    __nv_bfloat16 *xhi, *xlo, *h0hi, *h0lo, *h1hi, *h1lo, *dAhi, *dAlo, *dBhi, *dBlo;
    uint4 *fW0Th, *fW0Tl, *fW1Th, *fW1Tl, *fW2Th, *fW2Tl, *fW2nh, *fW2nl, *fW1nh, *fW1nl, *fW0nh, *fW0nl;
    cudaGetSymbolAddress((void**)&xhi, g_xhi);   cudaGetSymbolAddress((void**)&xlo, g_xlo);
    cudaGetSymbolAddress((void**)&h0hi, g_h0hi); cudaGetSymbolAddress((void**)&h0lo, g_h0lo);
    cudaGetSymbolAddress((void**)&h1hi, g_h1hi); cudaGetSymbolAddress((void**)&h1lo, g_h1lo);
    cudaGetSymbolAddress((void**)&dAhi, g_dAhi); cudaGetSymbolAddress((void**)&dAlo, g_dAlo);
    cudaGetSymbolAddress((void**)&dBhi, g_dBhi); cudaGetSymbolAddress((void**)&dBlo, g_dBlo);
    cudaGetSymbolAddress((void**)&fW0Th, g_fW0T_hi); cudaGetSymbolAddress((void**)&fW0Tl, g_fW0T_lo);
    cudaGetSymbolAddress((void**)&fW1Th, g_fW1T_hi); cudaGetSymbolAddress((void**)&fW1Tl, g_fW1T_lo);
    cudaGetSymbolAddress((void**)&fW2Th, g_fW2T_hi); cudaGetSymbolAddress((void**)&fW2Tl, g_fW2T_lo);
    cudaGetSymbolAddress((void**)&fW2nh, g_fW2n_hi); cudaGetSymbolAddress((void**)&fW2nl, g_fW2n_lo);
    cudaGetSymbolAddress((void**)&fW1nh, g_fW1n_hi); cudaGetSymbolAddress((void**)&fW1nl, g_fW1n_lo);
    cudaGetSymbolAddress((void**)&fW0nh, g_fW0n_hi); cudaGetSymbolAddress((void**)&fW0nl, g_fW0n_lo);

    // prep
    split_k<<<(BTOT * DDIM + 255) / 256, 256>>>(x, xhi, xlo, BTOT * DDIM);
    // forward weights: B[n][k] = W[k][n] (trans=1); backward: B[n][k] = W[n][k] (trans=0)
    pack_frag<<<64, 256>>>(W0, fW0Th, fW0Tl, 64, 512, 16, 4, 1);
    pack_frag<<<128, 256>>>(W1, fW1Th, fW1Tl, 512, 512, 16, 4, 1);
    pack_frag<<<128, 256>>>(W2, fW2Th, fW2Tl, 512, 512, 16, 4, 1);
    pack_frag<<<128, 256>>>(W2, fW2nh, fW2nl, 512, 512, 16, 4, 0);
    pack_frag<<<128, 256>>>(W1, fW1nh, fW1nl, 512, 512, 16, 4, 0);
    pack_frag<<<64, 256>>>(W0, fW0nh, fW0nl, 512, 64, 4, 2, 0);

    const int GRID = BTOT / 128;   // 512

    // L0: h0 = tanh(x @ W0 + b0)
    gemm_layer<64, 512, 0><<<GRID, 512>>>(xhi, xlo, fW0Th, fW0Tl, b0, nullptr,
                                          nullptr, nullptr, h0hi, h0lo, nullptr);
    // L1: h1 = tanh(h0 @ W1 + b1)
    gemm_layer<512, 512, 0><<<GRID, 512>>>(h0hi, h0lo, fW1Th, fW1Tl, b1, nullptr,
                                           nullptr, nullptr, h1hi, h1lo, nullptr);
    // L2 + seed: dA = (1 - tanh^2(h1 @ W2 + b2)) * W3
    gemm_layer<512, 512, 1><<<GRID, 512>>>(h1hi, h1lo, fW2Th, fW2Tl, b2, W3,
                                           nullptr, nullptr, dAhi, dAlo, nullptr);
    // B2: dB = (dA @ W2^T) * (1 - h1^2)
    gemm_layer<512, 512, 2><<<GRID, 512>>>(dAhi, dAlo, fW2nh, fW2nl, nullptr, nullptr,
                                           h1hi, h1lo, dBhi, dBlo, nullptr);
    // B1: dA = (dB @ W1^T) * (1 - h0^2)
    gemm_layer<512, 512, 2><<<GRID, 512>>>(dBhi, dBlo, fW1nh, fW1nl, nullptr, nullptr,
                                           h0hi, h0lo, dAhi, dAlo, nullptr);
    // F: out = symplectic(dA @ W0^T)
    gemm_layer<512, 64, 3><<<GRID, 512>>>(dAhi, dAlo, fW0nh, fW0nl, nullptr, nullptr,
                                          nullptr, nullptr, nullptr, nullptr, out);
}

// round 17
// speedup vs baseline: 3.4428x; 2.0851x over previous
#include <cuda_runtime.h>
#include <cuda_bf16.h>
#include <cstdint>

#define BTOT 65536
#define HDIM 512
#define DDIM 64

// ---------------- static device scratch ----------------
__device__ __nv_bfloat16 g_xhi[BTOT * DDIM], g_xlo[BTOT * DDIM];
__device__ __nv_bfloat16 g_h0hi[BTOT * HDIM], g_h0lo[BTOT * HDIM];
__device__ __nv_bfloat16 g_h1hi[BTOT * HDIM], g_h1lo[BTOT * HDIM];
__device__ __nv_bfloat16 g_dAhi[BTOT * HDIM], g_dAlo[BTOT * HDIM];
__device__ __nv_bfloat16 g_dBhi[BTOT * HDIM], g_dBlo[BTOT * HDIM];

// pre-packed B fragments, COALESCED layout:
// uint4 index = ((ktg*nG + ng)*JT + j)*32 + lane, JT = TPW/2
__device__ uint4 g_fW0T_hi[4096],  g_fW0T_lo[4096];    // KT=64,  NTOT=512
__device__ uint4 g_fW1T_hi[32768], g_fW1T_lo[32768];   // KT=512, NTOT=512
__device__ uint4 g_fW2T_hi[32768], g_fW2T_lo[32768];
__device__ uint4 g_fW2n_hi[32768], g_fW2n_lo[32768];
__device__ uint4 g_fW1n_hi[32768], g_fW1n_lo[32768];
__device__ uint4 g_fW0n_hi[4096],  g_fW0n_lo[4096];    // KT=512, NTOT=64

// ---------------- helpers ----------------
__device__ __forceinline__ uint32_t smem_u32(const void* p) {
    uint32_t a;
    asm("{ .reg .u64 t; cvta.to.shared.u64 t, %1; cvt.u32.u64 %0, t; }" : "=r"(a) : "l"(p));
    return a;
}
__device__ __forceinline__ uint32_t pk2(__nv_bfloat16 a, __nv_bfloat16 b) {
    return (uint32_t)__bfloat16_as_ushort(a) | ((uint32_t)__bfloat16_as_ushort(b) << 16);
}
__device__ __forceinline__ void ldsm4(uint32_t r[4], uint32_t addr) {
    asm volatile("ldmatrix.sync.aligned.m8n8.x4.shared.b16 {%0,%1,%2,%3}, [%4];"
                 : "=r"(r[0]), "=r"(r[1]), "=r"(r[2]), "=r"(r[3]) : "r"(addr));
}
__device__ __forceinline__ void mma16816(float c[4], const uint32_t a[4],
                                         uint32_t b0, uint32_t b1) {
    asm volatile(
        "mma.sync.aligned.m16n8k16.row.col.f32.bf16.bf16.f32 "
        "{%0,%1,%2,%3}, {%4,%5,%6,%7}, {%8,%9}, {%0,%1,%2,%3};"
        : "+f"(c[0]), "+f"(c[1]), "+f"(c[2]), "+f"(c[3])
        : "r"(a[0]), "r"(a[1]), "r"(a[2]), "r"(a[3]), "r"(b0), "r"(b1));
}
__device__ __forceinline__ uint32_t split2(float a, float b, uint32_t& lo) {
    __nv_bfloat16 ha = __float2bfloat16(a), hb = __float2bfloat16(b);
    __nv_bfloat16 la = __float2bfloat16(a - __bfloat162float(ha));
    __nv_bfloat16 lb = __float2bfloat16(b - __bfloat162float(hb));
    lo = pk2(la, lb);
    return pk2(ha, hb);
}
__device__ __forceinline__ float bflo(uint32_t u) {
    return __bfloat162float(__ushort_as_bfloat16((unsigned short)(u & 0xFFFF)));
}
__device__ __forceinline__ float bfhi(uint32_t u) {
    return __bfloat162float(__ushort_as_bfloat16((unsigned short)(u >> 16)));
}
__device__ __forceinline__ void cpasync16(uint32_t saddr, const void* g) {
    asm volatile("cp.async.ca.shared.global [%0], [%1], 16;" :: "r"(saddr), "l"(g));
}
__device__ __forceinline__ void cp_commit() {
    asm volatile("cp.async.commit_group;" ::: "memory");
}
template<int N>
__device__ __forceinline__ void cp_wait() {
    asm volatile("cp.async.wait_group %0;" :: "n"(N) : "memory");
}

// ---------------- prep kernels ----------------
__global__ void split_k(const float* __restrict__ in,
                        __nv_bfloat16* __restrict__ hi, __nv_bfloat16* __restrict__ lo,
                        int n) {
    int i = blockIdx.x * blockDim.x + threadIdx.x;
    if (i < n) {
        float v = in[i];
        __nv_bfloat16 h = __float2bfloat16(v);
        hi[i] = h;
        lo[i] = __float2bfloat16(v - __bfloat162float(h));
    }
}

// Pack B[n][k] (= W[k*NTOT+n] if trans else W[n*KT+k]) into coalesced fragment order.
__global__ void pack_frag(const float* __restrict__ W,
                          uint4* __restrict__ dhi, uint4* __restrict__ dlo,
                          int KT, int NTOT, int TPW, int nG, int trans) {
    const int JT = TPW / 2;
    const int total = (KT / 16) * nG * JT * 32;
    for (int i = blockIdx.x * blockDim.x + threadIdx.x; i < total;
         i += gridDim.x * blockDim.x) {
        int lane = i & 31;
        int r = i >> 5;
        int j = r % JT;
        int r2 = r / JT;
        int ng = r2 % nG;
        int kt = r2 / nG;
        int k0 = kt * 16 + 2 * (lane & 3);
        uint32_t h[4], l[4];
#pragma unroll
        for (int tt = 0; tt < 2; tt++) {
            int t = 2 * j + tt;
            int n = ng * TPW * 8 + t * 8 + (lane >> 2);
            float v0, v1, v2, v3;
            if (trans) {
                v0 = W[(size_t)(k0 + 0) * NTOT + n];
                v1 = W[(size_t)(k0 + 1) * NTOT + n];
                v2 = W[(size_t)(k0 + 8) * NTOT + n];
                v3 = W[(size_t)(k0 + 9) * NTOT + n];
            } else {
                v0 = W[(size_t)n * KT + k0 + 0];
                v1 = W[(size_t)n * KT + k0 + 1];
                v2 = W[(size_t)n * KT + k0 + 8];
                v3 = W[(size_t)n * KT + k0 + 9];
            }
            h[2 * tt + 0] = split2(v0, v1, l[2 * tt + 0]);
            h[2 * tt + 1] = split2(v2, v3, l[2 * tt + 1]);
        }
        dhi[i] = make_uint4(h[0], h[1], h[2], h[3]);
        dlo[i] = make_uint4(l[0], l[1], l[2], l[3]);
    }
}

// ---------------- GEMM layer (mma.sync, cp.async pipelined, single pass) ----------------
// D[r][n] = sum_k A[r][k]*B[n][k], 3-term bf16 split, fused epilogue.
// EPI: 0 tanh(D+bias); 1 (1-tanh^2(D+bias))*w3[n]; 2 D*(1-(Hhi+Hlo)^2); 3 symplectic fp32
template<int KT, int NTOT, int EPI>
__global__ void __launch_bounds__(512, 1)
gemm_layer(const __nv_bfloat16* __restrict__ Ahi, const __nv_bfloat16* __restrict__ Alo,
           const uint4* __restrict__ fhi, const uint4* __restrict__ flo,
           const float* __restrict__ bias, const float* __restrict__ w3,
           const __nv_bfloat16* __restrict__ Hhi, const __nv_bfloat16* __restrict__ Hlo,
           __nv_bfloat16* __restrict__ Ohi, __nv_bfloat16* __restrict__ Olo,
           float* __restrict__ Ofp) {
    constexpr int MROWS = (NTOT == 512) ? 64 : 128;   // rows per CTA
    constexpr int WMW = MROWS / 16;                   // warps along M (4 or 8)
    constexpr int WNW = 16 / WMW;                     // warps along N (4 or 2)
    constexpr int TPW = NTOT / (8 * WNW);             // n8-tiles per warp (16 or 4)
    constexpr int JT = TPW / 2;
    constexpr int nG = WNW;
    constexpr int NKC = KT / 64;
    constexpr int SROW = 72;                          // padded smem row (bf16)

    extern __shared__ __align__(16) char smem_raw[];
    __nv_bfloat16* sbase = reinterpret_cast<__nv_bfloat16*>(smem_raw);
    // layout: [buf(2)][plane(2)][MROWS][SROW]
    auto sptr = [&](int buf, int plane) {
        return sbase + (size_t)(buf * 2 + plane) * MROWS * SROW;
    };

    const int tid = threadIdx.x;
    const int lane = tid & 31;
    const int w = tid >> 5;
    const int wm = w % WMW;
    const int ng = w / WMW;
    const long row0 = (long)blockIdx.x * MROWS;

    const int lrow = 16 * wm + (lane & 15);
    const int lcol8 = (lane >> 4) << 3;

    // staging geometry: MROWS*8 16B-groups per plane, 512 threads
    constexpr int PER = (MROWS * 8) / 512;            // 1 or 2
    auto stage = [&](int kc, int buf) {
#pragma unroll
        for (int e = 0; e < PER; e++) {
            int idx = tid + e * 512;
            int r = idx >> 3, g8 = idx & 7;
            cpasync16(smem_u32(sptr(buf, 0) + r * SROW + g8 * 8),
                      Ahi + (row0 + r) * KT + kc * 64 + g8 * 8);
            cpasync16(smem_u32(sptr(buf, 1) + r * SROW + g8 * 8),
                      Alo + (row0 + r) * KT + kc * 64 + g8 * 8);
        }
    };

    float acc[TPW][4];
#pragma unroll
    for (int t = 0; t < TPW; t++)
#pragma unroll
        for (int q = 0; q < 4; q++) acc[t][q] = 0.f;

    stage(0, 0);
    cp_commit();

    for (int kc = 0; kc < NKC; kc++) {
        const int buf = kc & 1;
        if (kc + 1 < NKC) {
            stage(kc + 1, buf ^ 1);
            cp_commit();
            cp_wait<1>();
        } else {
            cp_wait<0>();
        }
        __syncthreads();

#pragma unroll
        for (int ks = 0; ks < 4; ks++) {
            const int ktg = kc * 4 + ks;
            uint32_t ah[4], al[4];
            ldsm4(ah, smem_u32(sptr(buf, 0) + lrow * SROW + ks * 16 + lcol8));
            ldsm4(al, smem_u32(sptr(buf, 1) + lrow * SROW + ks * 16 + lcol8));
            const uint4* bh = fhi + (size_t)(ktg * nG + ng) * JT * 32;
            const uint4* bl = flo + (size_t)(ktg * nG + ng) * JT * 32;
#pragma unroll
            for (int j = 0; j < JT; j++) {
                uint4 vh = bh[j * 32 + lane];
                uint4 vl = bl[j * 32 + lane];
                mma16816(acc[2 * j], ah, vh.x, vh.y);
                mma16816(acc[2 * j], ah, vl.x, vl.y);
                mma16816(acc[2 * j], al, vh.x, vh.y);
                mma16816(acc[2 * j + 1], ah, vh.z, vh.w);
                mma16816(acc[2 * j + 1], ah, vl.z, vl.w);
                mma16816(acc[2 * j + 1], al, vh.z, vh.w);
            }
        }
        __syncthreads();
    }

    // ---- epilogue ----
    const long rA = row0 + 16 * wm + (lane >> 2);   // rows rA, rA+8
    const int cb = ng * TPW * 8 + 2 * (lane & 3);
#pragma unroll
    for (int t = 0; t < TPW; t++) {
        const int c0 = cb + t * 8;
        float v00 = acc[t][0], v01 = acc[t][1], v10 = acc[t][2], v11 = acc[t][3];

        if (EPI == 0 || EPI == 1) {
            const float b0v = bias[c0], b1v = bias[c0 + 1];
            float t00 = tanhf(v00 + b0v), t01 = tanhf(v01 + b1v);
            float t10 = tanhf(v10 + b0v), t11 = tanhf(v11 + b1v);
            if (EPI == 1) {
                const float w0v = w3[c0], w1v = w3[c0 + 1];
                v00 = (1.f - t00 * t00) * w0v; v01 = (1.f - t01 * t01) * w1v;
                v10 = (1.f - t10 * t10) * w0v; v11 = (1.f - t11 * t11) * w1v;
            } else {
                v00 = t00; v01 = t01; v10 = t10; v11 = t11;
            }
        }
        if (EPI == 2) {
            uint32_t hh0 = *reinterpret_cast<const uint32_t*>(&Hhi[rA * NTOT + c0]);
            uint32_t hl0 = *reinterpret_cast<const uint32_t*>(&Hlo[rA * NTOT + c0]);
            uint32_t hh1 = *reinterpret_cast<const uint32_t*>(&Hhi[(rA + 8) * NTOT + c0]);
            uint32_t hl1 = *reinterpret_cast<const uint32_t*>(&Hlo[(rA + 8) * NTOT + c0]);
            float h00 = bflo(hh0) + bflo(hl0), h01 = bfhi(hh0) + bfhi(hl0);
            float h10 = bflo(hh1) + bflo(hl1), h11 = bfhi(hh1) + bfhi(hl1);
            v00 *= (1.f - h00 * h00); v01 *= (1.f - h01 * h01);
            v10 *= (1.f - h10 * h10); v11 *= (1.f - h11 * h11);
        }

        if (EPI == 3) {
            const int oc = (c0 + 32) & 63;
            const float sgn = (c0 < 32) ? -1.f : 1.f;
            *reinterpret_cast<float2*>(&Ofp[rA * 64 + oc]) =
                make_float2(sgn * v00, sgn * v01);
            *reinterpret_cast<float2*>(&Ofp[(rA + 8) * 64 + oc]) =
                make_float2(sgn * v10, sgn * v11);
        } else {
            uint32_t lo0, lo1;
            uint32_t hi0 = split2(v00, v01, lo0);
            uint32_t hi1 = split2(v10, v11, lo1);
            *reinterpret_cast<uint32_t*>(&Ohi[rA * NTOT + c0]) = hi0;
            *reinterpret_cast<uint32_t*>(&Olo[rA * NTOT + c0]) = lo0;
            *reinterpret_cast<uint32_t*>(&Ohi[(rA + 8) * NTOT + c0]) = hi1;
            *reinterpret_cast<uint32_t*>(&Olo[(rA + 8) * NTOT + c0]) = lo1;
        }
    }
}

// ---------------- launcher ----------------
extern "C" void kernel_launch(void* const* d_in, const int* in_sizes, int n_in,
                              void* d_out, int out_size) {
    // metadata order: t, x, W0, b0, W1, b1, W2, b2, W3, b3
    const float* x  = (const float*)d_in[1];
    const float* W0 = (const float*)d_in[2];
    const float* b0 = (const float*)d_in[3];
    const float* W1 = (const float*)d_in[4];
    const float* b1 = (const float*)d_in[5];
    const float* W2 = (const float*)d_in[6];
    const float* b2 = (const float*)d_in[7];
    const float* W3 = (const float*)d_in[8];
    float* out = (float*)d_out;

    __nv_bfloat16 *xhi, *xlo, *h0hi, *h0lo, *h1hi, *h1lo, *dAhi, *dAlo, *dBhi, *dBlo;
    uint4 *fW0Th, *fW0Tl, *fW1Th, *fW1Tl, *fW2Th, *fW2Tl, *fW2nh, *fW2nl, *fW1nh, *fW1nl, *fW0nh, *fW0nl;
    cudaGetSymbolAddress((void**)&xhi, g_xhi);   cudaGetSymbolAddress((void**)&xlo, g_xlo);
    cudaGetSymbolAddress((void**)&h0hi, g_h0hi); cudaGetSymbolAddress((void**)&h0lo, g_h0lo);
    cudaGetSymbolAddress((void**)&h1hi, g_h1hi); cudaGetSymbolAddress((void**)&h1lo, g_h1lo);
    cudaGetSymbolAddress((void**)&dAhi, g_dAhi); cudaGetSymbolAddress((void**)&dAlo, g_dAlo);
    cudaGetSymbolAddress((void**)&dBhi, g_dBhi); cudaGetSymbolAddress((void**)&dBlo, g_dBlo);
    cudaGetSymbolAddress((void**)&fW0Th, g_fW0T_hi); cudaGetSymbolAddress((void**)&fW0Tl, g_fW0T_lo);
    cudaGetSymbolAddress((void**)&fW1Th, g_fW1T_hi); cudaGetSymbolAddress((void**)&fW1Tl, g_fW1T_lo);
    cudaGetSymbolAddress((void**)&fW2Th, g_fW2T_hi); cudaGetSymbolAddress((void**)&fW2Tl, g_fW2T_lo);
    cudaGetSymbolAddress((void**)&fW2nh, g_fW2n_hi); cudaGetSymbolAddress((void**)&fW2nl, g_fW2n_lo);
    cudaGetSymbolAddress((void**)&fW1nh, g_fW1n_hi); cudaGetSymbolAddress((void**)&fW1nl, g_fW1n_lo);
    cudaGetSymbolAddress((void**)&fW0nh, g_fW0n_hi); cudaGetSymbolAddress((void**)&fW0nl, g_fW0n_lo);

    // prep
    split_k<<<(BTOT * DDIM + 255) / 256, 256>>>(x, xhi, xlo, BTOT * DDIM);
    pack_frag<<<64, 256>>>(W0, fW0Th, fW0Tl, 64, 512, 16, 4, 1);
    pack_frag<<<128, 256>>>(W1, fW1Th, fW1Tl, 512, 512, 16, 4, 1);
    pack_frag<<<128, 256>>>(W2, fW2Th, fW2Tl, 512, 512, 16, 4, 1);
    pack_frag<<<128, 256>>>(W2, fW2nh, fW2nl, 512, 512, 16, 4, 0);
    pack_frag<<<128, 256>>>(W1, fW1nh, fW1nl, 512, 512, 16, 4, 0);
    pack_frag<<<64, 256>>>(W0, fW0nh, fW0nl, 512, 64, 4, 2, 0);

    const int SM_N512 = 2 * 2 * 64 * 72 * 2;    // 36864 B
    const int SM_N64  = 2 * 2 * 128 * 72 * 2;   // 73728 B
    cudaFuncSetAttribute(gemm_layer<64, 512, 0>, cudaFuncAttributeMaxDynamicSharedMemorySize, SM_N512);
    cudaFuncSetAttribute(gemm_layer<512, 512, 0>, cudaFuncAttributeMaxDynamicSharedMemorySize, SM_N512);
    cudaFuncSetAttribute(gemm_layer<512, 512, 1>, cudaFuncAttributeMaxDynamicSharedMemorySize, SM_N512);
    cudaFuncSetAttribute(gemm_layer<512, 512, 2>, cudaFuncAttributeMaxDynamicSharedMemorySize, SM_N512);
    cudaFuncSetAttribute(gemm_layer<512, 64, 3>, cudaFuncAttributeMaxDynamicSharedMemorySize, SM_N64);

    const int G512 = BTOT / 64;    // 1024 CTAs (M=64)
    const int G64  = BTOT / 128;   // 512 CTAs (M=128, F layer)

    // L0: h0 = tanh(x @ W0 + b0)
    gemm_layer<64, 512, 0><<<G512, 512, SM_N512>>>(xhi, xlo, fW0Th, fW0Tl, b0, nullptr,
                                                   nullptr, nullptr, h0hi, h0lo, nullptr);
    // L1: h1 = tanh(h0 @ W1 + b1)
    gemm_layer<512, 512, 0><<<G512, 512, SM_N512>>>(h0hi, h0lo, fW1Th, fW1Tl, b1, nullptr,
                                                    nullptr, nullptr, h1hi, h1lo, nullptr);
    // L2 + seed: dA = (1 - tanh^2(h1 @ W2 + b2)) * W3
    gemm_layer<512, 512, 1><<<G512, 512, SM_N512>>>(h1hi, h1lo, fW2Th, fW2Tl, b2, W3,
                                                    nullptr, nullptr, dAhi, dAlo, nullptr);
    // B2: dB = (dA @ W2^T) * (1 - h1^2)
    gemm_layer<512, 512, 2><<<G512, 512, SM_N512>>>(dAhi, dAlo, fW2nh, fW2nl, nullptr, nullptr,
                                                    h1hi, h1lo, dBhi, dBlo, nullptr);
    // B1: dA = (dB @ W1^T) * (1 - h0^2)
    gemm_layer<512, 512, 2><<<G512, 512, SM_N512>>>(dBhi, dBlo, fW1nh, fW1nl, nullptr, nullptr,
                                                    h0hi, h0lo, dAhi, dAlo, nullptr);
    // F: out = symplectic(dA @ W0^T)
    gemm_layer<512, 64, 3><<<G64, 512, SM_N64>>>(dAhi, dAlo, fW0nh, fW0nl, nullptr, nullptr,
                                                 nullptr, nullptr, nullptr, nullptr, out);
}